// round 2
// baseline (speedup 1.0000x reference)
#include <cuda_runtime.h>

// Problem dims (fixed by the dataset: M=N=8192, D=512)
#define M_DIM 8192
#define N_DIM 8192
#define D_DIM 512
#define NBN   64   // number of 128-wide column blocks

// Scratch (no cudaMalloc allowed — __device__ globals per harness rules)
__device__ float g_xx[M_DIM];            // row norms of x
__device__ float g_yy[N_DIM];            // row norms of x_train
__device__ float g_partial[NBN * M_DIM]; // per-column-block partial sums

// ---------------------------------------------------------------------------
// Kernel 1: row squared-norms for x (blockIdx.y==0) and x_train (==1).
// One block per row, 128 threads, float4 loads (512 floats / row).
// ---------------------------------------------------------------------------
__global__ void row_norms_kernel(const float* __restrict__ X,
                                 const float* __restrict__ Y) {
    const int row = blockIdx.x;
    const float* src = (blockIdx.y == 0) ? X : Y;
    const float4 v = *(const float4*)(src + (size_t)row * D_DIM + threadIdx.x * 4);
    float s = v.x * v.x + v.y * v.y + v.z * v.z + v.w * v.w;
    #pragma unroll
    for (int off = 16; off > 0; off >>= 1)
        s += __shfl_down_sync(0xffffffffu, s, off);
    __shared__ float ws[4];
    const int lane = threadIdx.x & 31, w = threadIdx.x >> 5;
    if (lane == 0) ws[w] = s;
    __syncthreads();
    if (threadIdx.x == 0) {
        const float t = ws[0] + ws[1] + ws[2] + ws[3];
        if (blockIdx.y == 0) g_xx[row] = t; else g_yy[row] = t;
    }
}

// ---------------------------------------------------------------------------
// Kernel 2: fused tiled GEMM (xy) + RBF + weight reduction.
// BM=BN=128, BK=16, 256 threads, 8x8 register tile, stride-16 lane mapping.
// Each block (bm,bn) emits 128 partial row-sums into g_partial[bn][m].
// ---------------------------------------------------------------------------
__global__ __launch_bounds__(256)
void rbf_gemm_kernel(const float* __restrict__ X, const float* __restrict__ Y,
                     const float* __restrict__ gamma_p,
                     const float* __restrict__ W) {
    __shared__ float As[16][129];   // [k][m], padded: conflict-free transposed store
    __shared__ float Bs[16][129];   // [k][n]
    __shared__ float wsh[128];
    __shared__ float yysh[128];
    __shared__ float red[128][17];  // row-sum reduction scratch, padded

    const int bm = blockIdx.y, bn = blockIdx.x;
    const int tid = threadIdx.x;
    const int tx = tid & 15, ty = tid >> 4;
    const int rowBase = bm * 128, colBase = bn * 128;

    if (tid < 128) {
        wsh[tid]  = W[colBase + tid];
        yysh[tid] = g_yy[colBase + tid];
    }

    float acc[8][8];
    #pragma unroll
    for (int i = 0; i < 8; i++)
        #pragma unroll
        for (int j = 0; j < 8; j++) acc[i][j] = 0.0f;

    for (int k0 = 0; k0 < D_DIM; k0 += 16) {
        // Cooperative tile load: 128 rows x 16 k, as 512 float4 slots (2/thread)
        #pragma unroll
        for (int s = tid; s < 512; s += 256) {
            const int r = s >> 2, c4 = s & 3;
            const float4 va = *(const float4*)(X + (size_t)(rowBase + r) * D_DIM + k0 + c4 * 4);
            As[c4 * 4 + 0][r] = va.x; As[c4 * 4 + 1][r] = va.y;
            As[c4 * 4 + 2][r] = va.z; As[c4 * 4 + 3][r] = va.w;
            const float4 vb = *(const float4*)(Y + (size_t)(colBase + r) * D_DIM + k0 + c4 * 4);
            Bs[c4 * 4 + 0][r] = vb.x; Bs[c4 * 4 + 1][r] = vb.y;
            Bs[c4 * 4 + 2][r] = vb.z; Bs[c4 * 4 + 3][r] = vb.w;
        }
        __syncthreads();
        #pragma unroll
        for (int k = 0; k < 16; k++) {
            float a[8], b[8];
            #pragma unroll
            for (int i = 0; i < 8; i++) a[i] = As[k][i * 16 + ty];  // broadcast across tx
            #pragma unroll
            for (int j = 0; j < 8; j++) b[j] = Bs[k][j * 16 + tx];  // conflict-free
            #pragma unroll
            for (int i = 0; i < 8; i++)
                #pragma unroll
                for (int j = 0; j < 8; j++)
                    acc[i][j] = fmaf(a[i], b[j], acc[i][j]);
        }
        __syncthreads();
    }

    // Fused epilogue: sq = xx + yy - 2*xy; exp underflows to exactly 0 in fp32
    // for arg > ~104, so gate MUFU behind t < 110 (bit-exact vs fp32 reference).
    const float g = gamma_p[0];
    #pragma unroll
    for (int i = 0; i < 8; i++) {
        const float xxv = g_xx[rowBase + i * 16 + ty];
        float rs = 0.0f;
        #pragma unroll
        for (int j = 0; j < 8; j++) {
            const int nn = j * 16 + tx;
            const float sq = fmaxf(xxv + yysh[nn] - 2.0f * acc[i][j], 0.0f);
            const float t = g * sq;
            const float v = (t < 110.0f) ? __expf(-t) : 0.0f;
            rs = fmaf(v, wsh[nn], rs);
        }
        red[i * 16 + ty][tx] = rs;
    }
    __syncthreads();
    if (tid < 128) {
        float s = 0.0f;
        #pragma unroll
        for (int c = 0; c < 16; c++) s += red[tid][c];
        g_partial[(size_t)bn * M_DIM + rowBase + tid] = s;  // unique slot, no atomics
    }
}

// ---------------------------------------------------------------------------
// Kernel 3: deterministic final reduction over the 64 column blocks + bias.
// ---------------------------------------------------------------------------
__global__ void reduce_kernel(float* __restrict__ out,
                              const float* __restrict__ bias) {
    const int m = blockIdx.x * blockDim.x + threadIdx.x;
    float s = bias[0];
    #pragma unroll
    for (int bn = 0; bn < NBN; bn++)
        s += g_partial[(size_t)bn * M_DIM + m];
    out[m] = s;
}

// ---------------------------------------------------------------------------
// kernel_launch: inputs (metadata order): x[8192*512] f32, x_train[8192*512] f32,
// gamma[1] f32, weight[8192] f32, bias[1] f32. Output: 8192 f32.
// Graph-capturable: 3 plain launches, no sync, no alloc.
// ---------------------------------------------------------------------------
extern "C" void kernel_launch(void* const* d_in, const int* in_sizes, int n_in,
                              void* d_out, int out_size) {
    const float* x       = (const float*)d_in[0];
    const float* x_train = (const float*)d_in[1];
    const float* gamma   = (const float*)d_in[2];
    const float* weight  = (const float*)d_in[3];
    const float* bias    = (const float*)d_in[4];
    float* out = (float*)d_out;

    row_norms_kernel<<<dim3(M_DIM, 2), 128>>>(x, x_train);
    rbf_gemm_kernel<<<dim3(NBN, M_DIM / 128), 256>>>(x, x_train, gamma, weight);
    reduce_kernel<<<M_DIM / 256, 256>>>(out, bias);
}

// round 4
// speedup vs baseline: 6.9243x; 6.9243x over previous
#include <cuda_runtime.h>
#include <cuda_bf16.h>
#include <cstdint>

// Problem dims (fixed by dataset)
#define M_DIM 8192
#define N_DIM 8192
#define D_DIM 512
#define BM 128
#define BN 128
#define BK 32                 // bf16 elems per K-chunk
#define NCHUNK (D_DIM / BK)   // 16
#define NBN (N_DIM / BN)      // 64
#define STAGES 3
#define ROW_PITCH 80          // 64B data + 16B pad: conflict-free ldmatrix, 16B-aligned
#define STG_TILE 10240        // 128 rows * 80 B
#define STG_BYTES 20480       // A + B per stage

// SMEM offsets (dynamic)
#define OFF_Q   (STAGES * STG_BYTES)          // 61440: 128 floats (gamma*yy)
#define OFF_W   (OFF_Q + 512)                 // 61952: 128 floats (weight)
#define OFF_RED (OFF_W + 512)                 // 62464: 2 x 128 floats
#define SMEM_BYTES (OFF_RED + 1024)           // 63488

// ---------------- device scratch (no cudaMalloc allowed) ----------------
__device__ __nv_bfloat16 g_Xb[(size_t)M_DIM * D_DIM];   // 8 MB
__device__ __nv_bfloat16 g_Yb[(size_t)N_DIM * D_DIM];   // 8 MB
__device__ float g_xx[M_DIM];
__device__ float g_yy[N_DIM];
__device__ float g_partial[(size_t)NBN * M_DIM];        // 2 MB

__device__ __forceinline__ uint32_t smem_u32(const void* p) {
    uint32_t a;
    asm("{ .reg .u64 t; cvta.to.shared.u64 t, %1; cvt.u32.u64 %0, t; }" : "=r"(a) : "l"(p));
    return a;
}
__device__ __forceinline__ void cp_async16(uint32_t saddr, const void* gaddr) {
    asm volatile("cp.async.cg.shared.global [%0], [%1], 16;" :: "r"(saddr), "l"(gaddr));
}
#define CP_COMMIT() asm volatile("cp.async.commit_group;" ::: "memory")
__device__ __forceinline__ void ldmatrix_x4(uint32_t& r0, uint32_t& r1, uint32_t& r2,
                                            uint32_t& r3, uint32_t addr) {
    asm volatile("ldmatrix.sync.aligned.m8n8.x4.shared.b16 {%0,%1,%2,%3}, [%4];"
                 : "=r"(r0), "=r"(r1), "=r"(r2), "=r"(r3) : "r"(addr));
}
__device__ __forceinline__ void mma_bf16(float* c, uint32_t a0, uint32_t a1, uint32_t a2,
                                         uint32_t a3, uint32_t b0, uint32_t b1) {
    asm volatile("mma.sync.aligned.m16n8k16.row.col.f32.bf16.bf16.f32 "
                 "{%0,%1,%2,%3}, {%4,%5,%6,%7}, {%8,%9}, {%0,%1,%2,%3};"
                 : "+f"(c[0]), "+f"(c[1]), "+f"(c[2]), "+f"(c[3])
                 : "r"(a0), "r"(a1), "r"(a2), "r"(a3), "r"(b0), "r"(b1));
}

// ---------------------------------------------------------------------------
// Prologue: fp32 -> bf16 conversion fused with row squared-norms.
// ---------------------------------------------------------------------------
__global__ void prep_kernel(const float* __restrict__ X, const float* __restrict__ Y) {
    const int row = blockIdx.x;
    const bool isY = (blockIdx.y != 0);
    const float* src = isY ? Y : X;
    __nv_bfloat16* dst = isY ? g_Yb : g_Xb;

    const float4 v = *(const float4*)(src + (size_t)row * D_DIM + threadIdx.x * 4);
    float s = v.x * v.x + v.y * v.y + v.z * v.z + v.w * v.w;

    __nv_bfloat162 h0 = __floats2bfloat162_rn(v.x, v.y);
    __nv_bfloat162 h1 = __floats2bfloat162_rn(v.z, v.w);
    uint2 pk;
    pk.x = *reinterpret_cast<uint32_t*>(&h0);
    pk.y = *reinterpret_cast<uint32_t*>(&h1);
    *reinterpret_cast<uint2*>(dst + (size_t)row * D_DIM + threadIdx.x * 4) = pk;

    #pragma unroll
    for (int off = 16; off > 0; off >>= 1) s += __shfl_down_sync(0xffffffffu, s, off);
    __shared__ float ws[4];
    const int lane = threadIdx.x & 31, w = threadIdx.x >> 5;
    if (lane == 0) ws[w] = s;
    __syncthreads();
    if (threadIdx.x == 0) {
        const float t = ws[0] + ws[1] + ws[2] + ws[3];
        if (isY) g_yy[row] = t; else g_xx[row] = t;
    }
}

// ---------------------------------------------------------------------------
// Main kernel: mma.sync bf16 GEMM (128x128 tile, K=512) + fused RBF epilogue.
// 8 warps in 4(M) x 2(N); warp tile 32x64. 3-stage cp.async pipeline.
// ---------------------------------------------------------------------------
__device__ __forceinline__ void load_stage(char* smem, uint32_t sb, int s, int c,
                                           int rowBase, int colBase, int tid) {
    const int k0 = c * BK;
    // A: 512 x 16B transfers, B: 512 x 16B; 2 of each per thread.
    #pragma unroll
    for (int i = 0; i < 2; i++) {
        const int idx = tid + i * 256;
        const int r = idx >> 2, c16 = idx & 3;
        const uint32_t so = (uint32_t)(s * STG_BYTES + r * ROW_PITCH + c16 * 16);
        cp_async16(sb + so, g_Xb + (size_t)(rowBase + r) * D_DIM + k0 + c16 * 8);
        cp_async16(sb + so + STG_TILE, g_Yb + (size_t)(colBase + r) * D_DIM + k0 + c16 * 8);
    }
}

__global__ __launch_bounds__(256, 2)
void rbf_mma_kernel(const float* __restrict__ gamma_p, const float* __restrict__ W) {
    extern __shared__ char smem[];
    const uint32_t sb = smem_u32(smem);
    const int tid = threadIdx.x;
    const int w = tid >> 5, l = tid & 31;
    const int wm = w & 3, wn = w >> 2;         // 4 x 2 warp grid
    const int m0w = wm * 32, n0w = wn * 64;
    const int bn = blockIdx.x, bm = blockIdx.y;
    const int rowBase = bm * BM, colBase = bn * BN;

    const float g = gamma_p[0];
    if (tid < 128) {
        ((float*)(smem + OFF_Q))[tid] = g * g_yy[colBase + tid];
        ((float*)(smem + OFF_W))[tid] = W[colBase + tid];
    }

    float acc[2][8][4];
    #pragma unroll
    for (int mt = 0; mt < 2; mt++)
        #pragma unroll
        for (int nt = 0; nt < 8; nt++)
            #pragma unroll
            for (int i = 0; i < 4; i++) acc[mt][nt][i] = 0.0f;

    // prologue: preload stages 0,1
    load_stage(smem, sb, 0, 0, rowBase, colBase, tid); CP_COMMIT();
    load_stage(smem, sb, 1, 1, rowBase, colBase, tid); CP_COMMIT();

    // ldmatrix lane base addresses (A: rows=m, B: rows=n; col halves by l>>4)
    const uint32_t a_lane = (uint32_t)((m0w + (l & 15)) * ROW_PITCH + ((l >> 4) * 16));
    const uint32_t b_lane = (uint32_t)(STG_TILE + (n0w + (l & 15)) * ROW_PITCH + ((l >> 4) * 16));

    #pragma unroll 1
    for (int c = 0; c < NCHUNK; c++) {
        if (c == NCHUNK - 1) asm volatile("cp.async.wait_group 0;" ::: "memory");
        else                 asm volatile("cp.async.wait_group 1;" ::: "memory");
        __syncthreads();
        if (c + 2 < NCHUNK) {
            load_stage(smem, sb, (c + 2) % STAGES, c + 2, rowBase, colBase, tid);
            CP_COMMIT();
        }
        const uint32_t stg = sb + (uint32_t)((c % STAGES) * STG_BYTES);
        #pragma unroll
        for (int kk = 0; kk < 2; kk++) {                 // two k16 steps per BK=32
            const uint32_t ko = (uint32_t)(kk * 32);     // 16 bf16 = 32 B
            uint32_t a[2][4], b[4][4];
            #pragma unroll
            for (int mt = 0; mt < 2; mt++)
                ldmatrix_x4(a[mt][0], a[mt][1], a[mt][2], a[mt][3],
                            stg + a_lane + mt * (16 * ROW_PITCH) + ko);
            #pragma unroll
            for (int nt2 = 0; nt2 < 4; nt2++)
                ldmatrix_x4(b[nt2][0], b[nt2][1], b[nt2][2], b[nt2][3],
                            stg + b_lane + nt2 * (16 * ROW_PITCH) + ko);
            #pragma unroll
            for (int mt = 0; mt < 2; mt++)
                #pragma unroll
                for (int nt = 0; nt < 8; nt++) {
                    const int h = nt >> 1, o = nt & 1;   // ntile o of ldmatrix group h
                    mma_bf16(acc[mt][nt], a[mt][0], a[mt][1], a[mt][2], a[mt][3],
                             b[h][o], b[h][o + 2]);
                }
        }
    }
    __syncthreads();

    // ---- fused epilogue straight from register fragments ----
    // c-fragment m16n8: c0,c1 -> row l/4, cols (l%4)*2,+1 ; c2,c3 -> row l/4+8.
    const float* qsh = (const float*)(smem + OFF_Q);
    const float* wsh = (const float*)(smem + OFF_W);
    const float m2g = -2.0f * g;
    float rs[2][2] = {{0.0f, 0.0f}, {0.0f, 0.0f}};   // [mt][lo/hi]
    float gxx[2][2];
    #pragma unroll
    for (int mt = 0; mt < 2; mt++)
        #pragma unroll
        for (int h = 0; h < 2; h++)
            gxx[mt][h] = g * g_xx[rowBase + m0w + mt * 16 + (l >> 2) + 8 * h];

    #pragma unroll
    for (int mt = 0; mt < 2; mt++)
        #pragma unroll
        for (int nt = 0; nt < 8; nt++) {
            const int n = n0w + nt * 8 + (l & 3) * 2;
            const float q0 = qsh[n], q1 = qsh[n + 1];
            const float w0 = wsh[n], w1 = wsh[n + 1];
            const float* cc = acc[mt][nt];
            // exp underflows to exactly 0 in fp32 for arg > ~104: gate MUFU
            float t;
            t = fmaf(m2g, cc[0], gxx[mt][0] + q0);
            if (t < 110.0f) rs[mt][0] = fmaf(__expf(-fmaxf(t, 0.0f)), w0, rs[mt][0]);
            t = fmaf(m2g, cc[1], gxx[mt][0] + q1);
            if (t < 110.0f) rs[mt][0] = fmaf(__expf(-fmaxf(t, 0.0f)), w1, rs[mt][0]);
            t = fmaf(m2g, cc[2], gxx[mt][1] + q0);
            if (t < 110.0f) rs[mt][1] = fmaf(__expf(-fmaxf(t, 0.0f)), w0, rs[mt][1]);
            t = fmaf(m2g, cc[3], gxx[mt][1] + q1);
            if (t < 110.0f) rs[mt][1] = fmaf(__expf(-fmaxf(t, 0.0f)), w1, rs[mt][1]);
        }

    float* red = (float*)(smem + OFF_RED);   // [2][128]
    #pragma unroll
    for (int mt = 0; mt < 2; mt++)
        #pragma unroll
        for (int h = 0; h < 2; h++) {
            float v = rs[mt][h];
            v += __shfl_xor_sync(0xffffffffu, v, 1);
            v += __shfl_xor_sync(0xffffffffu, v, 2);
            if ((l & 3) == 0)
                red[wn * 128 + m0w + mt * 16 + (l >> 2) + 8 * h] = v;
        }
    __syncthreads();
    if (tid < 128)
        g_partial[(size_t)bn * M_DIM + rowBase + tid] = red[tid] + red[128 + tid];
}

// ---------------------------------------------------------------------------
// Final deterministic reduction over 64 column blocks + bias.
// ---------------------------------------------------------------------------
__global__ void reduce_kernel(float* __restrict__ out, const float* __restrict__ bias) {
    const int m = blockIdx.x * blockDim.x + threadIdx.x;
    float s = bias[0];
    #pragma unroll
    for (int b = 0; b < NBN; b++) s += g_partial[(size_t)b * M_DIM + m];
    out[m] = s;
}

// ---------------------------------------------------------------------------
extern "C" void kernel_launch(void* const* d_in, const int* in_sizes, int n_in,
                              void* d_out, int out_size) {
    const float* x       = (const float*)d_in[0];
    const float* x_train = (const float*)d_in[1];
    const float* gamma   = (const float*)d_in[2];
    const float* weight  = (const float*)d_in[3];
    const float* bias    = (const float*)d_in[4];
    float* out = (float*)d_out;

    cudaFuncSetAttribute(rbf_mma_kernel, cudaFuncAttributeMaxDynamicSharedMemorySize, SMEM_BYTES);

    prep_kernel<<<dim3(M_DIM, 2), 128>>>(x, x_train);
    rbf_mma_kernel<<<dim3(NBN, M_DIM / BM), 256, SMEM_BYTES>>>(gamma, weight);
    reduce_kernel<<<M_DIM / 256, 256>>>(out, bias);
}

// round 5
// speedup vs baseline: 7.6074x; 1.0987x over previous
#include <cuda_runtime.h>
#include <cuda_bf16.h>
#include <cstdint>

// Problem dims (fixed by dataset)
#define M_DIM 8192
#define N_DIM 8192
#define D_DIM 512
#define BM 128
#define BN 128
#define BK 64                 // fp8 elems per K-chunk = 64 B rows (same bytes as R3)
#define NCHUNK (D_DIM / BK)   // 8
#define NBN (N_DIM / BN)      // 64
#define STAGES 3
#define ROW_PITCH 80          // 64B data + 16B pad: conflict-free ldmatrix, 16B-aligned
#define STG_TILE 10240        // 128 rows * 80 B
#define STG_BYTES 20480       // A + B per stage

// SMEM offsets (dynamic)
#define OFF_Q   (STAGES * STG_BYTES)          // 61440: 128 floats (gamma*yy)
#define OFF_W   (OFF_Q + 512)                 // 61952: 128 floats (weight)
#define OFF_RED (OFF_W + 512)                 // 62464: 2 x 128 floats
#define SMEM_BYTES (OFF_RED + 1024)           // 63488

// ---------------- device scratch (no cudaMalloc allowed) ----------------
__device__ uint8_t g_Xq[(size_t)M_DIM * D_DIM];   // 4 MB, e4m3
__device__ uint8_t g_Yq[(size_t)N_DIM * D_DIM];   // 4 MB, e4m3
__device__ float g_xx[M_DIM];
__device__ float g_yy[N_DIM];
__device__ float g_partial[(size_t)NBN * M_DIM];  // 2 MB

__device__ __forceinline__ uint32_t smem_u32(const void* p) {
    uint32_t a;
    asm("{ .reg .u64 t; cvta.to.shared.u64 t, %1; cvt.u32.u64 %0, t; }" : "=r"(a) : "l"(p));
    return a;
}
__device__ __forceinline__ void cp_async16(uint32_t saddr, const void* gaddr) {
    asm volatile("cp.async.cg.shared.global [%0], [%1], 16;" :: "r"(saddr), "l"(gaddr));
}
#define CP_COMMIT() asm volatile("cp.async.commit_group;" ::: "memory")
__device__ __forceinline__ void ldmatrix_x4(uint32_t& r0, uint32_t& r1, uint32_t& r2,
                                            uint32_t& r3, uint32_t addr) {
    asm volatile("ldmatrix.sync.aligned.m8n8.x4.shared.b16 {%0,%1,%2,%3}, [%4];"
                 : "=r"(r0), "=r"(r1), "=r"(r2), "=r"(r3) : "r"(addr));
}
// fp8 e4m3 MMA, k32, fp32 accum. Fragment bytes coincide with bf16-k16 fragments,
// so the same ldmatrix addressing applies (32 B per matrix row either way).
__device__ __forceinline__ void mma_fp8(float* c, uint32_t a0, uint32_t a1, uint32_t a2,
                                        uint32_t a3, uint32_t b0, uint32_t b1) {
    asm volatile("mma.sync.aligned.m16n8k32.row.col.f32.e4m3.e4m3.f32 "
                 "{%0,%1,%2,%3}, {%4,%5,%6,%7}, {%8,%9}, {%0,%1,%2,%3};"
                 : "+f"(c[0]), "+f"(c[1]), "+f"(c[2]), "+f"(c[3])
                 : "r"(a0), "r"(a1), "r"(a2), "r"(a3), "r"(b0), "r"(b1));
}
// pack 2 floats -> 2 e4m3 bytes (low byte = first arg)
__device__ __forceinline__ uint16_t pack_e4m3x2(float lo, float hi) {
    uint16_t d;
    asm("cvt.rn.satfinite.e4m3x2.f32 %0, %1, %2;" : "=h"(d) : "f"(hi), "f"(lo));
    return d;
}

// ---------------------------------------------------------------------------
// Prologue: fp32 -> e4m3 conversion fused with row squared-norms (fp32 norms).
// ---------------------------------------------------------------------------
__global__ void prep_kernel(const float* __restrict__ X, const float* __restrict__ Y) {
    const int row = blockIdx.x;
    const bool isY = (blockIdx.y != 0);
    const float* src = isY ? Y : X;
    uint8_t* dst = isY ? g_Yq : g_Xq;

    const float4 v = *(const float4*)(src + (size_t)row * D_DIM + threadIdx.x * 4);
    float s = v.x * v.x + v.y * v.y + v.z * v.z + v.w * v.w;

    const uint32_t p0 = pack_e4m3x2(v.x, v.y);
    const uint32_t p1 = pack_e4m3x2(v.z, v.w);
    *reinterpret_cast<uint32_t*>(dst + (size_t)row * D_DIM + threadIdx.x * 4) =
        p0 | (p1 << 16);

    #pragma unroll
    for (int off = 16; off > 0; off >>= 1) s += __shfl_down_sync(0xffffffffu, s, off);
    __shared__ float ws[4];
    const int lane = threadIdx.x & 31, w = threadIdx.x >> 5;
    if (lane == 0) ws[w] = s;
    __syncthreads();
    if (threadIdx.x == 0) {
        const float t = ws[0] + ws[1] + ws[2] + ws[3];
        if (isY) g_yy[row] = t; else g_xx[row] = t;
    }
}

// ---------------------------------------------------------------------------
// Main kernel: fp8 mma.sync GEMM (128x128 tile, K=512) + fused RBF epilogue.
// 8 warps in 4(M) x 2(N); warp tile 32x64. 3-stage cp.async pipeline.
// ---------------------------------------------------------------------------
__device__ __forceinline__ void load_stage(uint32_t sb, int s, int c,
                                           int rowBase, int colBase, int tid) {
    const int k0 = c * BK;   // byte offset within a row (1 B per elem)
    #pragma unroll
    for (int i = 0; i < 2; i++) {
        const int idx = tid + i * 256;
        const int r = idx >> 2, c16 = idx & 3;
        const uint32_t so = (uint32_t)(s * STG_BYTES + r * ROW_PITCH + c16 * 16);
        cp_async16(sb + so, g_Xq + (size_t)(rowBase + r) * D_DIM + k0 + c16 * 16);
        cp_async16(sb + so + STG_TILE, g_Yq + (size_t)(colBase + r) * D_DIM + k0 + c16 * 16);
    }
}

__global__ __launch_bounds__(256, 2)
void rbf_mma_kernel(const float* __restrict__ gamma_p, const float* __restrict__ W) {
    extern __shared__ char smem[];
    const uint32_t sb = smem_u32(smem);
    const int tid = threadIdx.x;
    const int w = tid >> 5, l = tid & 31;
    const int wm = w & 3, wn = w >> 2;         // 4 x 2 warp grid
    const int m0w = wm * 32, n0w = wn * 64;
    const int bn = blockIdx.x, bm = blockIdx.y;
    const int rowBase = bm * BM, colBase = bn * BN;

    const float g = gamma_p[0];
    if (tid < 128) {
        ((float*)(smem + OFF_Q))[tid] = g * g_yy[colBase + tid];
        ((float*)(smem + OFF_W))[tid] = W[colBase + tid];
    }

    float acc[2][8][4];
    #pragma unroll
    for (int mt = 0; mt < 2; mt++)
        #pragma unroll
        for (int nt = 0; nt < 8; nt++)
            #pragma unroll
            for (int i = 0; i < 4; i++) acc[mt][nt][i] = 0.0f;

    load_stage(sb, 0, 0, rowBase, colBase, tid); CP_COMMIT();
    load_stage(sb, 1, 1, rowBase, colBase, tid); CP_COMMIT();

    // ldmatrix lane base addresses (16 rows covered per x4; halves by l>>4)
    const uint32_t a_lane = (uint32_t)((m0w + (l & 15)) * ROW_PITCH + ((l >> 4) * 16));
    const uint32_t b_lane = (uint32_t)(STG_TILE + (n0w + (l & 15)) * ROW_PITCH + ((l >> 4) * 16));

    #pragma unroll 1
    for (int c = 0; c < NCHUNK; c++) {
        if (c == NCHUNK - 1) asm volatile("cp.async.wait_group 0;" ::: "memory");
        else                 asm volatile("cp.async.wait_group 1;" ::: "memory");
        __syncthreads();
        if (c + 2 < NCHUNK) {
            load_stage(sb, (c + 2) % STAGES, c + 2, rowBase, colBase, tid);
            CP_COMMIT();
        }
        const uint32_t stg = sb + (uint32_t)((c % STAGES) * STG_BYTES);
        #pragma unroll
        for (int kk = 0; kk < 2; kk++) {                 // two k32 steps per BK=64
            const uint32_t ko = (uint32_t)(kk * 32);     // 32 fp8 = 32 B
            uint32_t a[2][4], b[4][4];
            #pragma unroll
            for (int mt = 0; mt < 2; mt++)
                ldmatrix_x4(a[mt][0], a[mt][1], a[mt][2], a[mt][3],
                            stg + a_lane + mt * (16 * ROW_PITCH) + ko);
            #pragma unroll
            for (int nt2 = 0; nt2 < 4; nt2++)
                ldmatrix_x4(b[nt2][0], b[nt2][1], b[nt2][2], b[nt2][3],
                            stg + b_lane + nt2 * (16 * ROW_PITCH) + ko);
            #pragma unroll
            for (int mt = 0; mt < 2; mt++)
                #pragma unroll
                for (int nt = 0; nt < 8; nt++) {
                    const int h = nt >> 1, o = nt & 1;
                    mma_fp8(acc[mt][nt], a[mt][0], a[mt][1], a[mt][2], a[mt][3],
                            b[h][o], b[h][o + 2]);
                }
        }
    }
    __syncthreads();

    // ---- fused epilogue straight from register fragments ----
    const float* qsh = (const float*)(smem + OFF_Q);
    const float* wsh = (const float*)(smem + OFF_W);
    const float m2g = -2.0f * g;
    float rs[2][2] = {{0.0f, 0.0f}, {0.0f, 0.0f}};   // [mt][lo/hi]
    float gxx[2][2];
    #pragma unroll
    for (int mt = 0; mt < 2; mt++)
        #pragma unroll
        for (int h = 0; h < 2; h++)
            gxx[mt][h] = g * g_xx[rowBase + m0w + mt * 16 + (l >> 2) + 8 * h];

    #pragma unroll
    for (int mt = 0; mt < 2; mt++)
        #pragma unroll
        for (int nt = 0; nt < 8; nt++) {
            const int n = n0w + nt * 8 + (l & 3) * 2;
            const float q0 = qsh[n], q1 = qsh[n + 1];
            const float w0 = wsh[n], w1 = wsh[n + 1];
            const float* cc = acc[mt][nt];
            // exp underflows to exactly 0 in fp32 for arg > ~104: gate MUFU
            float t;
            t = fmaf(m2g, cc[0], gxx[mt][0] + q0);
            if (t < 110.0f) rs[mt][0] = fmaf(__expf(-fmaxf(t, 0.0f)), w0, rs[mt][0]);
            t = fmaf(m2g, cc[1], gxx[mt][0] + q1);
            if (t < 110.0f) rs[mt][0] = fmaf(__expf(-fmaxf(t, 0.0f)), w1, rs[mt][0]);
            t = fmaf(m2g, cc[2], gxx[mt][1] + q0);
            if (t < 110.0f) rs[mt][1] = fmaf(__expf(-fmaxf(t, 0.0f)), w0, rs[mt][1]);
            t = fmaf(m2g, cc[3], gxx[mt][1] + q1);
            if (t < 110.0f) rs[mt][1] = fmaf(__expf(-fmaxf(t, 0.0f)), w1, rs[mt][1]);
        }

    float* red = (float*)(smem + OFF_RED);   // [2][128]
    #pragma unroll
    for (int mt = 0; mt < 2; mt++)
        #pragma unroll
        for (int h = 0; h < 2; h++) {
            float v = rs[mt][h];
            v += __shfl_xor_sync(0xffffffffu, v, 1);
            v += __shfl_xor_sync(0xffffffffu, v, 2);
            if ((l & 3) == 0)
                red[wn * 128 + m0w + mt * 16 + (l >> 2) + 8 * h] = v;
        }
    __syncthreads();
    if (tid < 128)
        g_partial[(size_t)bn * M_DIM + rowBase + tid] = red[tid] + red[128 + tid];
}

// ---------------------------------------------------------------------------
// Final deterministic reduction over 64 column blocks + bias.
// ---------------------------------------------------------------------------
__global__ void reduce_kernel(float* __restrict__ out, const float* __restrict__ bias) {
    const int m = blockIdx.x * blockDim.x + threadIdx.x;
    float s = bias[0];
    #pragma unroll
    for (int b = 0; b < NBN; b++) s += g_partial[(size_t)b * M_DIM + m];
    out[m] = s;
}

// ---------------------------------------------------------------------------
extern "C" void kernel_launch(void* const* d_in, const int* in_sizes, int n_in,
                              void* d_out, int out_size) {
    const float* x       = (const float*)d_in[0];
    const float* x_train = (const float*)d_in[1];
    const float* gamma   = (const float*)d_in[2];
    const float* weight  = (const float*)d_in[3];
    const float* bias    = (const float*)d_in[4];
    float* out = (float*)d_out;

    cudaFuncSetAttribute(rbf_mma_kernel, cudaFuncAttributeMaxDynamicSharedMemorySize, SMEM_BYTES);

    prep_kernel<<<dim3(M_DIM, 2), 128>>>(x, x_train);
    rbf_mma_kernel<<<dim3(NBN, M_DIM / BM), 256, SMEM_BYTES>>>(gamma, weight);
    reduce_kernel<<<M_DIM / 256, 256>>>(out, bias);
}